// round 2
// baseline (speedup 1.0000x reference)
#include <cuda_runtime.h>
#include <cuda_bf16.h>
#include <cstdint>

// ============================================================================
// MajFC on GB300 (no tcgen05: harness PTX target is compute_103, not 103a).
//
// Math: per 3-group, clip(sum,-1,1) = 0.5*(x0w0 + x1w1 + x2w2 - (x0x1x2)(w0w1w2))
// over signs. So out = 1.125 * <X", W"> with augmented K = 3072 + 1024 = 4096
// ±1 vectors (W"'s product column negated). Bit-pack ±1 -> XOR+POPC GEMM:
//   dot = 4096 - 2*popc(xbits ^ wbits)   =>   out = 4608 - 2.25*mismatch.
// ============================================================================

#define BROWS 256
#define CIN   3072
#define COUT  1024
#define NGRP  1024
#define KW    128            // 4096 bits = 128 uint32 words per row

__device__ __align__(16) uint32_t g_Xb[BROWS * KW];   // 128 KB
__device__ __align__(16) uint32_t g_Wb[COUT  * KW];   // 512 KB

// ---------------------------------------------------------------------------
// Pack kernels. bit = 1 <=> sign +1. Region 1: raw element signs (96 words).
// Region 2: 3-group product signs (32 words); W's product bit is flipped
// (the -prod term folded in). Region boundaries are multiples of 32 so no
// warp straddles branches and __ballot_sync lane order == bit order.
// ---------------------------------------------------------------------------
__global__ void pack_x_kernel(const float* __restrict__ x) {
    int t = blockIdx.x * blockDim.x + threadIdx.x;
    if (t < BROWS * CIN) {
        int row = t / CIN, col = t % CIN;
        unsigned bit = x[(size_t)row * CIN + col] > 0.f;
        unsigned word = __ballot_sync(0xFFFFFFFFu, bit);
        if ((t & 31) == 0) g_Xb[row * KW + (col >> 5)] = word;
    } else {
        int u = t - BROWS * CIN;            // 0 .. BROWS*NGRP-1
        int row = u >> 10, g = u & 1023;
        const float* p = x + (size_t)row * CIN + g * 3;
        unsigned b = (unsigned)(p[0] > 0.f) ^ (unsigned)(p[1] > 0.f)
                   ^ (unsigned)(p[2] > 0.f);          // parity -> product sign
        unsigned word = __ballot_sync(0xFFFFFFFFu, b);
        if ((u & 31) == 0) g_Xb[row * KW + 96 + (g >> 5)] = word;
    }
}

__global__ void pack_w_kernel(const float* __restrict__ w) {
    int t = blockIdx.x * blockDim.x + threadIdx.x;
    if (t < COUT * CIN) {
        int row = t / CIN, col = t % CIN;
        unsigned bit = w[(size_t)row * CIN + col] > 0.f;
        unsigned word = __ballot_sync(0xFFFFFFFFu, bit);
        if ((t & 31) == 0) g_Wb[row * KW + (col >> 5)] = word;
    } else {
        int u = t - COUT * CIN;
        int row = u >> 10, g = u & 1023;
        const float* p = w + (size_t)row * CIN + g * 3;
        unsigned b = 1u ^ (unsigned)(p[0] > 0.f) ^ (unsigned)(p[1] > 0.f)
                        ^ (unsigned)(p[2] > 0.f);     // flipped: -prod folded
        unsigned word = __ballot_sync(0xFFFFFFFFu, b);
        if ((u & 31) == 0) g_Wb[row * KW + 96 + (g >> 5)] = word;
    }
}

// ---------------------------------------------------------------------------
// Binary GEMM: out[256,1024]. CTA tile 64(m) x 32(n), 256 threads,
// thread tile 4(m) x 2(n). K staged in SMEM in two 64-word chunks.
// Thread map: mi = tid>>4 (0..15), ni = tid&15. Within a warp mi spans 2
// values (A reads = 2-address broadcast, distinct banks) and ni spans 16
// (B reads hit 16 distinct banks via pad-65 rows). Conflict-free.
// ---------------------------------------------------------------------------
#define GM 64
#define GN 32
#define CK 64
#define SPITCH (CK + 1)

__global__ void __launch_bounds__(256, 2) maj_gemm_kernel(float* __restrict__ out) {
    __shared__ uint32_t Xs[GM][SPITCH];   // 64 x 65 x 4B = 16.25 KB
    __shared__ uint32_t Ws[GN][SPITCH];   //  8.125 KB

    int tid = threadIdx.x;
    int m0 = blockIdx.y * GM;
    int n0 = blockIdx.x * GN;
    int mi = tid >> 4;          // 0..15
    int ni = tid & 15;          // 0..15

    int acc[4][2] = {{0,0},{0,0},{0,0},{0,0}};

    for (int kc = 0; kc < KW; kc += CK) {
        // Load A chunk: 64 rows x 16 uint4 = 1024 uint4, 4 per thread.
#pragma unroll
        for (int p = 0; p < 4; p++) {
            int q = p * 256 + tid;
            int row = q >> 4, qw = (q & 15) << 2;
            uint4 v = *reinterpret_cast<const uint4*>(
                &g_Xb[(size_t)(m0 + row) * KW + kc + qw]);
            Xs[row][qw + 0] = v.x; Xs[row][qw + 1] = v.y;
            Xs[row][qw + 2] = v.z; Xs[row][qw + 3] = v.w;
        }
        // Load B chunk: 32 rows x 16 uint4 = 512 uint4, 2 per thread.
#pragma unroll
        for (int p = 0; p < 2; p++) {
            int q = p * 256 + tid;
            int row = q >> 4, qw = (q & 15) << 2;
            uint4 v = *reinterpret_cast<const uint4*>(
                &g_Wb[(size_t)(n0 + row) * KW + kc + qw]);
            Ws[row][qw + 0] = v.x; Ws[row][qw + 1] = v.y;
            Ws[row][qw + 2] = v.z; Ws[row][qw + 3] = v.w;
        }
        __syncthreads();

#pragma unroll 8
        for (int k = 0; k < CK; k++) {
            uint32_t xv0 = Xs[mi * 4 + 0][k];
            uint32_t xv1 = Xs[mi * 4 + 1][k];
            uint32_t xv2 = Xs[mi * 4 + 2][k];
            uint32_t xv3 = Xs[mi * 4 + 3][k];
            uint32_t wv0 = Ws[ni * 2 + 0][k];
            uint32_t wv1 = Ws[ni * 2 + 1][k];
            acc[0][0] += __popc(xv0 ^ wv0);
            acc[0][1] += __popc(xv0 ^ wv1);
            acc[1][0] += __popc(xv1 ^ wv0);
            acc[1][1] += __popc(xv1 ^ wv1);
            acc[2][0] += __popc(xv2 ^ wv0);
            acc[2][1] += __popc(xv2 ^ wv1);
            acc[3][0] += __popc(xv3 ^ wv0);
            acc[3][1] += __popc(xv3 ^ wv1);
        }
        __syncthreads();
    }

    // out = 1.125 * (4096 - 2*mismatch) = 4608 - 2.25*mismatch
#pragma unroll
    for (int r = 0; r < 4; r++) {
        int m = m0 + mi * 4 + r;
        float* o = out + (size_t)m * COUT + n0 + ni * 2;
        o[0] = 4608.0f - 2.25f * (float)acc[r][0];
        o[1] = 4608.0f - 2.25f * (float)acc[r][1];
    }
}

// ---------------------------------------------------------------------------
extern "C" void kernel_launch(void* const* d_in, const int* in_sizes, int n_in,
                              void* d_out, int out_size) {
    const float* x = (const float*)d_in[0];   // [256, 3072]
    const float* w = (const float*)d_in[1];   // [1024, 3072]
    float* out = (float*)d_out;               // [256, 1024] float32

    int xthreads = BROWS * CIN + BROWS * NGRP;   // 1,048,576
    int wthreads = COUT  * CIN + COUT  * NGRP;   // 4,194,304
    pack_x_kernel<<<xthreads / 256, 256>>>(x);
    pack_w_kernel<<<wthreads / 256, 256>>>(w);

    dim3 grid(COUT / GN, BROWS / GM);            // (32, 4) = 128 CTAs
    maj_gemm_kernel<<<grid, 256>>>(out);
}

// round 3
// speedup vs baseline: 1.4290x; 1.4290x over previous
#include <cuda_runtime.h>
#include <cuda_bf16.h>
#include <cstdint>

// ============================================================================
// MajFC:  out = 1.125 * <X", W">  with augmented ±1 vectors (K = 3072 + 1024):
//   per 3-group, clip(sum,-1,1) = 0.5*(x0w0 + x1w1 + x2w2 - (x0x1x2)(w0w1w2)).
// Bit-packed:  out = 4608 - 2.25 * popc(xbits ^ wbits)  over 128 words.
// Bit order is a fixed permutation, identical for X and W (XOR-popc invariant).
// ============================================================================

#define BROWS 256
#define CIN   3072
#define COUT  1024
#define KW    128            // 4096 bits per row

__device__ __align__(16) uint32_t g_Xb[BROWS * KW];   // 128 KB
__device__ __align__(16) uint32_t g_Wb[COUT  * KW];   // 512 KB

// ---------------------------------------------------------------------------
// Unified single-pass pack. One warp = one 96-float segment (32 groups of 3).
// Lane i reads cols 3i..3i+2 -> 3 element bits + 1 product bit; 4 ballots
// emit 3 element words (region 1) + 1 product word (region 2, W negated).
// ---------------------------------------------------------------------------
#define XSEGS (BROWS * 32)           // 8192 warps
#define WSEGS (COUT  * 32)           // 32768 warps
#define PACK_WARPS (XSEGS + WSEGS)   // 40960

__global__ void pack_kernel(const float* __restrict__ x,
                            const float* __restrict__ w) {
    int gw   = (blockIdx.x * blockDim.x + threadIdx.x) >> 5;
    int lane = threadIdx.x & 31;

    const float* src;
    uint32_t*    dst;
    unsigned flip;
    int seg;
    if (gw < XSEGS) {
        int row = gw >> 5; seg = gw & 31;
        src = x + (size_t)row * CIN;
        dst = g_Xb + (size_t)row * KW;
        flip = 0u;
    } else {
        int u = gw - XSEGS;
        int row = u >> 5; seg = u & 31;
        src = w + (size_t)row * CIN;
        dst = g_Wb + (size_t)row * KW;
        flip = 1u;                      // -prod(W) folded into the bit
    }

    const float* p = src + seg * 96 + lane * 3;
    unsigned b0 = p[0] > 0.f;
    unsigned b1 = p[1] > 0.f;
    unsigned b2 = p[2] > 0.f;
    unsigned w0 = __ballot_sync(0xFFFFFFFFu, b0);
    unsigned w1 = __ballot_sync(0xFFFFFFFFu, b1);
    unsigned w2 = __ballot_sync(0xFFFFFFFFu, b2);
    unsigned wp = __ballot_sync(0xFFFFFFFFu, b0 ^ b1 ^ b2 ^ flip);

    if (lane == 0) {
        dst[seg * 3 + 0] = w0;
        dst[seg * 3 + 1] = w1;
        dst[seg * 3 + 2] = w2;
        dst[96 + seg]    = wp;
    }
}

// ---------------------------------------------------------------------------
// Binary GEMM: CTA tile 64(m) x 32(n), 256 threads, thread tile 4x2,
// K staged in SMEM (two 64-word chunks), uint2 (k-pair) shared loads.
// Pitch 66 (even) keeps 8B alignment; A-reads broadcast, B-reads 2-way.
// ---------------------------------------------------------------------------
#define GM 64
#define GN 32
#define CK 64
#define SP 66

__global__ void __launch_bounds__(256, 2) maj_gemm_kernel(float* __restrict__ out) {
    __shared__ uint32_t Xs[GM][SP];
    __shared__ uint32_t Ws[GN][SP];

    int tid = threadIdx.x;
    int m0 = blockIdx.y * GM;
    int n0 = blockIdx.x * GN;
    int mi = tid >> 4;          // 0..15
    int ni = tid & 15;          // 0..15

    int acc[4][2] = {{0,0},{0,0},{0,0},{0,0}};

    for (int kc = 0; kc < KW; kc += CK) {
#pragma unroll
        for (int p = 0; p < 4; p++) {            // A: 64 rows x 16 uint4
            int q = p * 256 + tid;
            int row = q >> 4, qw = (q & 15) << 2;
            uint4 v = *reinterpret_cast<const uint4*>(
                &g_Xb[(size_t)(m0 + row) * KW + kc + qw]);
            *reinterpret_cast<uint2*>(&Xs[row][qw])     = make_uint2(v.x, v.y);
            *reinterpret_cast<uint2*>(&Xs[row][qw + 2]) = make_uint2(v.z, v.w);
        }
#pragma unroll
        for (int p = 0; p < 2; p++) {            // B: 32 rows x 16 uint4
            int q = p * 256 + tid;
            int row = q >> 4, qw = (q & 15) << 2;
            uint4 v = *reinterpret_cast<const uint4*>(
                &g_Wb[(size_t)(n0 + row) * KW + kc + qw]);
            *reinterpret_cast<uint2*>(&Ws[row][qw])     = make_uint2(v.x, v.y);
            *reinterpret_cast<uint2*>(&Ws[row][qw + 2]) = make_uint2(v.z, v.w);
        }
        __syncthreads();

#pragma unroll 8
        for (int k = 0; k < CK; k += 2) {
            uint2 x0 = *reinterpret_cast<const uint2*>(&Xs[mi * 4 + 0][k]);
            uint2 x1 = *reinterpret_cast<const uint2*>(&Xs[mi * 4 + 1][k]);
            uint2 x2 = *reinterpret_cast<const uint2*>(&Xs[mi * 4 + 2][k]);
            uint2 x3 = *reinterpret_cast<const uint2*>(&Xs[mi * 4 + 3][k]);
            uint2 v0 = *reinterpret_cast<const uint2*>(&Ws[ni * 2 + 0][k]);
            uint2 v1 = *reinterpret_cast<const uint2*>(&Ws[ni * 2 + 1][k]);
            acc[0][0] += __popc(x0.x ^ v0.x) + __popc(x0.y ^ v0.y);
            acc[0][1] += __popc(x0.x ^ v1.x) + __popc(x0.y ^ v1.y);
            acc[1][0] += __popc(x1.x ^ v0.x) + __popc(x1.y ^ v0.y);
            acc[1][1] += __popc(x1.x ^ v1.x) + __popc(x1.y ^ v1.y);
            acc[2][0] += __popc(x2.x ^ v0.x) + __popc(x2.y ^ v0.y);
            acc[2][1] += __popc(x2.x ^ v1.x) + __popc(x2.y ^ v1.y);
            acc[3][0] += __popc(x3.x ^ v0.x) + __popc(x3.y ^ v0.y);
            acc[3][1] += __popc(x3.x ^ v1.x) + __popc(x3.y ^ v1.y);
        }
        __syncthreads();
    }

    // out = 1.125 * (4096 - 2*mismatch) = 4608 - 2.25*mismatch
#pragma unroll
    for (int r = 0; r < 4; r++) {
        int m = m0 + mi * 4 + r;
        float* o = out + (size_t)m * COUT + n0 + ni * 2;
        o[0] = 4608.0f - 2.25f * (float)acc[r][0];
        o[1] = 4608.0f - 2.25f * (float)acc[r][1];
    }
}

// ---------------------------------------------------------------------------
extern "C" void kernel_launch(void* const* d_in, const int* in_sizes, int n_in,
                              void* d_out, int out_size) {
    const float* x = (const float*)d_in[0];   // [256, 3072]
    const float* w = (const float*)d_in[1];   // [1024, 3072]
    float* out = (float*)d_out;               // [256, 1024] float32

    pack_kernel<<<PACK_WARPS * 32 / 256, 256>>>(x, w);

    dim3 grid(COUT / GN, BROWS / GM);         // (32, 4) = 128 CTAs
    maj_gemm_kernel<<<grid, 256>>>(out);
}

// round 4
// speedup vs baseline: 1.4484x; 1.0135x over previous
#include <cuda_runtime.h>
#include <cuda_bf16.h>
#include <cstdint>

// ============================================================================
// MajFC:  out = 1.125 * <X", W">  with augmented ±1 vectors (K = 3072 + 1024):
//   per 3-group, clip(sum,-1,1) = 0.5*(x0w0 + x1w1 + x2w2 - (x0x1x2)(w0w1w2)).
// Bit-packed:  out = 4608 - 2.25 * popc(xbits ^ wbits)  over 128 words.
// ============================================================================

#define BROWS 256
#define CIN   3072
#define COUT  1024
#define KW    128            // 4096 bits per row

__device__ __align__(16) uint32_t g_Xb[BROWS * KW];   // 128 KB
__device__ __align__(16) uint32_t g_Wb[COUT  * KW];   // 512 KB

// ---------------------------------------------------------------------------
// Unified single-pass pack. One warp = one 96-float segment (32 groups of 3).
// ---------------------------------------------------------------------------
#define XSEGS (BROWS * 32)           // 8192 warps
#define WSEGS (COUT  * 32)           // 32768 warps
#define PACK_WARPS (XSEGS + WSEGS)   // 40960

__global__ void pack_kernel(const float* __restrict__ x,
                            const float* __restrict__ w) {
    int gw   = (blockIdx.x * blockDim.x + threadIdx.x) >> 5;
    int lane = threadIdx.x & 31;

    const float* src;
    uint32_t*    dst;
    unsigned flip;
    int seg;
    if (gw < XSEGS) {
        int row = gw >> 5; seg = gw & 31;
        src = x + (size_t)row * CIN;
        dst = g_Xb + (size_t)row * KW;
        flip = 0u;
    } else {
        int u = gw - XSEGS;
        int row = u >> 5; seg = u & 31;
        src = w + (size_t)row * CIN;
        dst = g_Wb + (size_t)row * KW;
        flip = 1u;                      // -prod(W) folded into the bit
    }

    const float* p = src + seg * 96 + lane * 3;
    unsigned b0 = p[0] > 0.f;
    unsigned b1 = p[1] > 0.f;
    unsigned b2 = p[2] > 0.f;
    unsigned w0 = __ballot_sync(0xFFFFFFFFu, b0);
    unsigned w1 = __ballot_sync(0xFFFFFFFFu, b1);
    unsigned w2 = __ballot_sync(0xFFFFFFFFu, b2);
    unsigned wp = __ballot_sync(0xFFFFFFFFu, b0 ^ b1 ^ b2 ^ flip);

    if (lane == 0) {
        dst[seg * 3 + 0] = w0;
        dst[seg * 3 + 1] = w1;
        dst[seg * 3 + 2] = w2;
        dst[96 + seg]    = wp;
    }
}

// ---------------------------------------------------------------------------
// Binary GEMM: CTA tile 32(m) x 16(n), 128 threads, thread tile 2x2,
// FULL K resident in SMEM (one sync), grid = 8 x 64 = 512 CTAs.
// Pitch 130 words: row base mod 128B = 8*row -> all inner-loop LDS.64
// conflict-free (W rows 2ni -> 16ni mod 128 distinct; X rows likewise).
// ---------------------------------------------------------------------------
#define GM 32
#define GN 16
#define SP 130

__global__ void __launch_bounds__(128, 6) maj_gemm_kernel(float* __restrict__ out) {
    __shared__ uint32_t Xs[GM][SP];   // 16.25 KB
    __shared__ uint32_t Ws[GN][SP];   //  8.125 KB

    int tid = threadIdx.x;
    int n0 = blockIdx.x * GN;         // grid.x = 64
    int m0 = blockIdx.y * GM;         // grid.y = 8

    // Stage both bit-tiles: 48 rows x 32 uint4 = 1536 uint4, 12 per thread.
#pragma unroll
    for (int p = 0; p < 12; p++) {
        int idx = p * 128 + tid;
        int row = idx >> 5, c = (idx & 31) << 2;
        const uint32_t* src = (row < GM)
            ? &g_Xb[(size_t)(m0 + row) * KW + c]
            : &g_Wb[(size_t)(n0 + row - GM) * KW + c];
        uint4 v = *reinterpret_cast<const uint4*>(src);
        uint32_t* d = (row < GM) ? &Xs[row][c] : &Ws[row - GM][c];
        *reinterpret_cast<uint2*>(d)     = make_uint2(v.x, v.y);   // 8B-aligned:
        *reinterpret_cast<uint2*>(d + 2) = make_uint2(v.z, v.w);   // SP even
    }
    __syncthreads();

    int mi = tid >> 3;                // 0..15 -> m rows 2mi, 2mi+1
    int ni = tid & 7;                 // 0..7  -> n rows 2ni, 2ni+1
    const uint32_t* xa = &Xs[mi * 2][0];
    const uint32_t* xb = &Xs[mi * 2 + 1][0];
    const uint32_t* wa = &Ws[ni * 2][0];
    const uint32_t* wb = &Ws[ni * 2 + 1][0];

    int a00 = 0, a01 = 0, a10 = 0, a11 = 0;
#pragma unroll 16
    for (int k = 0; k < KW; k += 2) {
        uint2 x0 = *reinterpret_cast<const uint2*>(&xa[k]);
        uint2 x1 = *reinterpret_cast<const uint2*>(&xb[k]);
        uint2 v0 = *reinterpret_cast<const uint2*>(&wa[k]);
        uint2 v1 = *reinterpret_cast<const uint2*>(&wb[k]);
        a00 += __popc(x0.x ^ v0.x) + __popc(x0.y ^ v0.y);
        a01 += __popc(x0.x ^ v1.x) + __popc(x0.y ^ v1.y);
        a10 += __popc(x1.x ^ v0.x) + __popc(x1.y ^ v0.y);
        a11 += __popc(x1.x ^ v1.x) + __popc(x1.y ^ v1.y);
    }

    // out = 1.125 * (4096 - 2*mismatch) = 4608 - 2.25*mismatch
    int m = m0 + mi * 2, n = n0 + ni * 2;
    float* o = out + (size_t)m * COUT + n;
    *reinterpret_cast<float2*>(o) =
        make_float2(4608.0f - 2.25f * (float)a00, 4608.0f - 2.25f * (float)a01);
    *reinterpret_cast<float2*>(o + COUT) =
        make_float2(4608.0f - 2.25f * (float)a10, 4608.0f - 2.25f * (float)a11);
}

// ---------------------------------------------------------------------------
extern "C" void kernel_launch(void* const* d_in, const int* in_sizes, int n_in,
                              void* d_out, int out_size) {
    const float* x = (const float*)d_in[0];   // [256, 3072]
    const float* w = (const float*)d_in[1];   // [1024, 3072]
    float* out = (float*)d_out;               // [256, 1024] float32

    pack_kernel<<<PACK_WARPS * 32 / 256, 256>>>(x, w);

    dim3 grid(COUT / GN, BROWS / GM);         // (64, 8) = 512 CTAs
    maj_gemm_kernel<<<grid, 128>>>(out);
}